// round 5
// baseline (speedup 1.0000x reference)
#include <cuda_runtime.h>
#include <cuda_bf16.h>
#include <cstdint>

// Problem constants
#define Nn 32
#define Kk 32
#define Tt 128
#define Hh 768
#define NEGINF (-1e20f)

// Output layout (concatenated float32):
// score:            [0, 1024)
// shifted_encoded:  [1024, 1024+3145728)
// shifted_mask:     [3146752, 3146752+4096)
// shifted_use:      [3150848, 3150848+24576)
// shifted_index:    [3175424, 3175424+4096)
#define OFF_SCORE   0
#define OFF_ENC     1024
#define OFF_MASK    3146752
#define OFF_USE     3150848
#define OFF_IDX     3175424

// Scratch (no allocations allowed -> device globals)
__device__ float g_cqk[Nn * Hh];   // cqk_pro
__device__ float g_v[Nn * Hh];     // W_k^T @ cqk_pro  (per n)
__device__ float g_c[Nn];          // b_k . cqk_pro[n]

// ---------------------------------------------------------------------------
// Kernel 0: init scratch. g_cqk = b_cqk broadcast (bias), g_v = 0, g_c = 0.
// ---------------------------------------------------------------------------
__global__ __launch_bounds__(256) void init_kernel(const float* __restrict__ b_cqk) {
    int i = blockIdx.x * blockDim.x + threadIdx.x;   // grid covers 24576
    if (i < Nn * Hh) {
        g_cqk[i] = b_cqk[i % Hh];
        g_v[i] = 0.f;
    }
    if (i < Nn) g_c[i] = 0.f;
}

// ---------------------------------------------------------------------------
// Kernel 1: cqk_pro[n,h] += sum_j cqk[n,j] * W_cqk[h,j]
//   cqk[n,j] = (j<768) ? ce1[n,2,j] : tk[n, j-768]
// Tiled GEMM M=32(n) x N=768(h), K=1536. Block tile 32n x 64h, K split x8.
// 128 threads, 4x4 micro-tile per thread, float4-vectorized over K.
// ---------------------------------------------------------------------------
__global__ __launch_bounds__(128) void gemm1_kernel(const float* __restrict__ ce1,
                                                    const float* __restrict__ tk,
                                                    const float* __restrict__ Wc) {
    __shared__ float As[32 * 36];  // [n][36], 32 valid k per chunk
    __shared__ float Bs[64 * 36];  // [h][36]

    const int h0    = blockIdx.x * 64;
    const int kbase = blockIdx.y * 192;       // split of K=1536 into 8
    const int tid   = threadIdx.x;
    const int tn    = tid >> 4;               // 0..7  -> n group tn*4..tn*4+3
    const int th    = tid & 15;               // 0..15 -> h group th*4..th*4+3

    float acc[4][4];
#pragma unroll
    for (int i = 0; i < 4; i++)
#pragma unroll
        for (int j = 0; j < 4; j++) acc[i][j] = 0.f;

    for (int c = 0; c < 6; c++) {
        const int k0 = kbase + c * 32;        // chunk of 32 K (whole chunk on one side of 768)
        // load A tile: 32n x 32k = 256 float4, 2 per thread
#pragma unroll
        for (int r = 0; r < 2; r++) {
            int idx = tid + 128 * r;
            int n = idx >> 3;
            int k4 = (idx & 7) * 4;
            int j = k0 + k4;
            const float* src = (j < Hh) ? (ce1 + n * (3 * Hh) + 2 * Hh + j)
                                        : (tk + n * Hh + (j - Hh));
            float4 v = *(const float4*)src;
            float* d = &As[n * 36 + k4];
            d[0] = v.x; d[1] = v.y; d[2] = v.z; d[3] = v.w;
        }
        // load B tile: 64h x 32k = 512 float4, 4 per thread
#pragma unroll
        for (int r = 0; r < 4; r++) {
            int idx = tid + 128 * r;
            int hh = idx >> 3;
            int k4 = (idx & 7) * 4;
            float4 v = *(const float4*)(Wc + (size_t)(h0 + hh) * (2 * Hh) + k0 + k4);
            float* d = &Bs[hh * 36 + k4];
            d[0] = v.x; d[1] = v.y; d[2] = v.z; d[3] = v.w;
        }
        __syncthreads();
#pragma unroll
        for (int k4 = 0; k4 < 8; k4++) {
            float4 a4[4], b4[4];
#pragma unroll
            for (int i = 0; i < 4; i++) a4[i] = *(float4*)&As[(tn * 4 + i) * 36 + k4 * 4];
#pragma unroll
            for (int j = 0; j < 4; j++) b4[j] = *(float4*)&Bs[(th * 4 + j) * 36 + k4 * 4];
#pragma unroll
            for (int i = 0; i < 4; i++)
#pragma unroll
                for (int j = 0; j < 4; j++)
                    acc[i][j] += a4[i].x * b4[j].x + a4[i].y * b4[j].y +
                                 a4[i].z * b4[j].z + a4[i].w * b4[j].w;
        }
        __syncthreads();
    }
#pragma unroll
    for (int i = 0; i < 4; i++)
#pragma unroll
        for (int j = 0; j < 4; j++)
            atomicAdd(&g_cqk[(tn * 4 + i) * Hh + h0 + th * 4 + j], acc[i][j]);
}

// ---------------------------------------------------------------------------
// Kernel 2: v[n,h] += sum_g cqk_pro[n,g] * W_k[g,h]   (K=768, split x4)
//           + special tile (blockIdx.x==12): c[n] += sum_g cqk_pro[n,g]*b_k[g]
// ---------------------------------------------------------------------------
__global__ __launch_bounds__(128) void gemm2_kernel(const float* __restrict__ Wk,
                                                    const float* __restrict__ bk) {
    const int tid   = threadIdx.x;
    const int kbase = blockIdx.y * 192;       // split of K=768 into 4

    if (blockIdx.x == 12) {
        // c[n] partial dot with b_k
        int w = tid >> 5, lane = tid & 31;
        for (int n = w; n < Nn; n += 4) {
            float s = 0.f;
#pragma unroll
            for (int m = 0; m < 6; m++) {
                int g = kbase + m * 32 + lane;
                s += g_cqk[n * Hh + g] * bk[g];
            }
#pragma unroll
            for (int o = 16; o > 0; o >>= 1) s += __shfl_xor_sync(0xffffffffu, s, o);
            if (lane == 0) atomicAdd(&g_c[n], s);
        }
        return;
    }

    __shared__ float As[32 * 33];  // [n][33]
    __shared__ float Bs[32 * 68];  // [kk][68] : 64 h contiguous

    const int h0 = blockIdx.x * 64;
    const int tn = tid >> 4;
    const int th = tid & 15;

    float4 acc[4];
#pragma unroll
    for (int i = 0; i < 4; i++) acc[i] = make_float4(0.f, 0.f, 0.f, 0.f);

    for (int c = 0; c < 6; c++) {
        const int k0 = kbase + c * 32;
        // A tile: 32n x 32k
#pragma unroll
        for (int r = 0; r < 2; r++) {
            int idx = tid + 128 * r;
            int n = idx >> 3;
            int k4 = (idx & 7) * 4;
            float4 v = *(const float4*)(g_cqk + n * Hh + k0 + k4);
            float* d = &As[n * 33 + k4];
            d[0] = v.x; d[1] = v.y; d[2] = v.z; d[3] = v.w;
        }
        // B tile: 32kk x 64h (contiguous over h)
#pragma unroll
        for (int r = 0; r < 4; r++) {
            int idx = tid + 128 * r;
            int kk = idx >> 4;
            int h4 = (idx & 15) * 4;
            *(float4*)&Bs[kk * 68 + h4] =
                *(const float4*)(Wk + (size_t)(k0 + kk) * Hh + h0 + h4);
        }
        __syncthreads();
#pragma unroll
        for (int kk = 0; kk < 32; kk++) {
            float4 b4 = *(float4*)&Bs[kk * 68 + th * 4];
#pragma unroll
            for (int i = 0; i < 4; i++) {
                float a = As[(tn * 4 + i) * 33 + kk];
                acc[i].x += a * b4.x;
                acc[i].y += a * b4.y;
                acc[i].z += a * b4.z;
                acc[i].w += a * b4.w;
            }
        }
        __syncthreads();
    }
#pragma unroll
    for (int i = 0; i < 4; i++) {
        float* dst = &g_v[(tn * 4 + i) * Hh + h0 + th * 4];
        atomicAdd(dst + 0, acc[i].x);
        atomicAdd(dst + 1, acc[i].y);
        atomicAdd(dst + 2, acc[i].z);
        atomicAdd(dst + 3, acc[i].w);
    }
}

// ---------------------------------------------------------------------------
// Kernel 3: score[n,k] = pe1[n,k,:].v[n,:] + c[n], masked by ck_mask (int32!)
// warp per (n,k) -> 1024 warps
// ---------------------------------------------------------------------------
__global__ __launch_bounds__(256) void score_kernel(const float* __restrict__ pe1,
                                                    const int* __restrict__ ckm,
                                                    float* __restrict__ out) {
    int w = (blockIdx.x * blockDim.x + threadIdx.x) >> 5;
    int lane = threadIdx.x & 31;
    if (w >= Nn * Kk) return;
    int n = w >> 5, k = w & 31;
    const float* p = pe1 + (size_t)(n * Kk + k) * Hh;
    const float* v = g_v + n * Hh;
    float s = 0.f;
#pragma unroll
    for (int m = 0; m < Hh / 32; m++) {
        int h = lane + m * 32;
        s += p[h] * v[h];
    }
#pragma unroll
    for (int o = 16; o > 0; o >>= 1) s += __shfl_xor_sync(0xffffffffu, s, o);
    if (lane == 0) {
        s += g_c[n];
        out[OFF_SCORE + n * Kk + k] = (ckm[n * Kk + k] != 0) ? s : NEGINF;
    }
}

// ---------------------------------------------------------------------------
// Kernel 4: gather copy (float4 vectorized). Masks are int32 elements.
// units: 786432 enc + 6144 use + 1024 mask + 1024 idx = 794624
// ---------------------------------------------------------------------------
__global__ __launch_bounds__(256) void gather_kernel(const float* __restrict__ pe0,
                                                     const float* __restrict__ pe1,
                                                     const int* __restrict__ pm,
                                                     const int* __restrict__ label,
                                                     const int* __restrict__ ptok,
                                                     float* __restrict__ out) {
    unsigned u = blockIdx.x * blockDim.x + threadIdx.x;
    if (u < 786432u) {
        int n = u / 24576u;           // 128*768/4 float4 per n
        int rem = u % 24576u;
        int l = label[n];
        float4 v = *(const float4*)(pe0 + (size_t)(n * Kk + l) * (Tt * Hh) + (size_t)rem * 4);
        *(float4*)(out + OFF_ENC + (size_t)u * 4) = v;
    } else if (u < 786432u + 6144u) {
        int i = u - 786432u;
        int n = i / 192, rem = i % 192;
        int l = label[n];
        float4 v = *(const float4*)(pe1 + (size_t)(n * Kk + l) * Hh + rem * 4);
        *(float4*)(out + OFF_USE + (size_t)i * 4) = v;
    } else if (u < 786432u + 6144u + 1024u) {
        int i = u - 792576u;
        int n = i / 32, rem = i % 32;       // 32 int4 units per (n) row of T=128 ints
        int l = label[n];
        int4 m = *(const int4*)(pm + (size_t)(n * Kk + l) * Tt + rem * 4);
        float4 v = make_float4(m.x ? 1.f : 0.f, m.y ? 1.f : 0.f,
                               m.z ? 1.f : 0.f, m.w ? 1.f : 0.f);
        *(float4*)(out + OFF_MASK + (size_t)i * 4) = v;
    } else if (u < 794624u) {
        int i = u - 793600u;
        int n = i / 32, rem = i % 32;
        int l = label[n];
        int4 t = *(const int4*)(ptok + (size_t)(n * Kk + l) * Tt + rem * 4);
        float4 v = make_float4((float)t.x, (float)t.y, (float)t.z, (float)t.w);
        *(float4*)(out + OFF_IDX + (size_t)i * 4) = v;
    }
}

// ---------------------------------------------------------------------------
extern "C" void kernel_launch(void* const* d_in, const int* in_sizes, int n_in,
                              void* d_out, int out_size) {
    const float* ce1   = (const float*)d_in[0];   // contexts_encoded_1 (32,3,768)
    const float* tk    = (const float*)d_in[1];   // tracked_knowledge_use (32,768)
    const float* pe0   = (const float*)d_in[2];   // pool_encoded_0 (32,32,128,768)
    const float* pe1   = (const float*)d_in[3];   // pool_encoded_1 (32,32,768)
    const int*   pm    = (const int*)d_in[4];     // pool_mask (32,32,128) bool->int32
    const int*   ckm   = (const int*)d_in[5];     // ck_mask (32,32) bool->int32
    const int*   label = (const int*)d_in[6];     // (32,)
    const int*   ptok  = (const int*)d_in[7];     // pool_tokens (32,32,128)
    const float* Wc    = (const float*)d_in[8];   // W_cqk (768,1536)
    const float* bc    = (const float*)d_in[9];   // b_cqk (768,)
    const float* Wk    = (const float*)d_in[10];  // W_k (768,768)
    const float* bk    = (const float*)d_in[11];  // b_k (768,)
    float* out = (float*)d_out;

    init_kernel<<<96, 256>>>(bc);
    gemm1_kernel<<<dim3(12, 8), 128>>>(ce1, tk, Wc);
    gemm2_kernel<<<dim3(13, 4), 128>>>(Wk, bk);
    score_kernel<<<128, 256>>>(pe1, ckm, out);
    gather_kernel<<<3104, 256>>>(pe0, pe1, pm, label, ptok, out);
}

// round 6
// speedup vs baseline: 1.0087x; 1.0087x over previous
#include <cuda_runtime.h>
#include <cuda_bf16.h>
#include <cstdint>

// Problem constants
#define Nn 32
#define Kk 32
#define Tt 128
#define Hh 768
#define NEGINF (-1e20f)

// Output layout (concatenated float32)
#define OFF_SCORE   0
#define OFF_ENC     1024
#define OFF_MASK    3146752
#define OFF_USE     3150848
#define OFF_IDX     3175424

#define SPLIT1 8   // K=1536 split into 8 x 192
#define SPLIT2 4   // K=768  split into 4 x 192

// Scratch (device globals; partial sums -> no init kernel, no atomics)
__device__ float g_cqk_part[SPLIT1][Nn * Hh];  // partial cqk_pro (bias NOT included)
__device__ float g_v_part[SPLIT2][Nn * Hh];    // partial v
__device__ float g_c_part[SPLIT2][Nn];         // partial c = bk . cqk_pro

// ---------------------------------------------------------------------------
// Kernel 1: g_cqk_part[by][n][h] = sum_{j in [by*192, by*192+192)} cqk[n,j]*Wc[h,j]
//   cqk[n,j] = (j<768) ? ce1[n,2,j] : tk[n, j-768]
// grid (12, 8), 128 threads, 32n x 64h tile, 4x4 micro-tile.
// ---------------------------------------------------------------------------
__global__ __launch_bounds__(128) void gemm1_kernel(const float* __restrict__ ce1,
                                                    const float* __restrict__ tk,
                                                    const float* __restrict__ Wc) {
    __shared__ float As[32 * 36];
    __shared__ float Bs[64 * 36];

    const int h0    = blockIdx.x * 64;
    const int by    = blockIdx.y;
    const int kbase = by * 192;
    const int tid   = threadIdx.x;
    const int tn    = tid >> 4;
    const int th    = tid & 15;

    float acc[4][4];
#pragma unroll
    for (int i = 0; i < 4; i++)
#pragma unroll
        for (int j = 0; j < 4; j++) acc[i][j] = 0.f;

    for (int c = 0; c < 6; c++) {
        const int k0 = kbase + c * 32;   // whole 32-chunk lies on one side of 768
#pragma unroll
        for (int r = 0; r < 2; r++) {
            int idx = tid + 128 * r;
            int n = idx >> 3;
            int k4 = (idx & 7) * 4;
            int j = k0 + k4;
            const float* src = (j < Hh) ? (ce1 + n * (3 * Hh) + 2 * Hh + j)
                                        : (tk + n * Hh + (j - Hh));
            float4 v = *(const float4*)src;
            float* d = &As[n * 36 + k4];
            d[0] = v.x; d[1] = v.y; d[2] = v.z; d[3] = v.w;
        }
#pragma unroll
        for (int r = 0; r < 4; r++) {
            int idx = tid + 128 * r;
            int hh = idx >> 3;
            int k4 = (idx & 7) * 4;
            float4 v = *(const float4*)(Wc + (size_t)(h0 + hh) * (2 * Hh) + k0 + k4);
            float* d = &Bs[hh * 36 + k4];
            d[0] = v.x; d[1] = v.y; d[2] = v.z; d[3] = v.w;
        }
        __syncthreads();
#pragma unroll
        for (int k4 = 0; k4 < 8; k4++) {
            float4 a4[4], b4[4];
#pragma unroll
            for (int i = 0; i < 4; i++) a4[i] = *(float4*)&As[(tn * 4 + i) * 36 + k4 * 4];
#pragma unroll
            for (int j = 0; j < 4; j++) b4[j] = *(float4*)&Bs[(th * 4 + j) * 36 + k4 * 4];
#pragma unroll
            for (int i = 0; i < 4; i++)
#pragma unroll
                for (int j = 0; j < 4; j++)
                    acc[i][j] += a4[i].x * b4[j].x + a4[i].y * b4[j].y +
                                 a4[i].z * b4[j].z + a4[i].w * b4[j].w;
        }
        __syncthreads();
    }
#pragma unroll
    for (int i = 0; i < 4; i++) {
        float4 o = make_float4(acc[i][0], acc[i][1], acc[i][2], acc[i][3]);
        *(float4*)&g_cqk_part[by][(tn * 4 + i) * Hh + h0 + th * 4] = o;
    }
}

// ---------------------------------------------------------------------------
// Kernel 2: g_v_part[by][n][h] = sum_{g in K-range} cqk_pro[n,g] * Wk[g,h]
//   cqk_pro[n,g] = sum_p g_cqk_part[p][n][g] + bc[g]
// bx==12: g_c_part[by][n] = sum_{g in K-range} cqk_pro[n,g] * bk[g]
// grid (13, 4), 128 threads.
// ---------------------------------------------------------------------------
__global__ __launch_bounds__(128) void gemm2_kernel(const float* __restrict__ Wk,
                                                    const float* __restrict__ bk,
                                                    const float* __restrict__ bc) {
    const int tid   = threadIdx.x;
    const int by    = blockIdx.y;
    const int kbase = by * 192;

    if (blockIdx.x == 12) {
        int w = tid >> 5, lane = tid & 31;
        for (int n = w; n < Nn; n += 4) {
            float s = 0.f;
#pragma unroll
            for (int m = 0; m < 6; m++) {
                int g = kbase + m * 32 + lane;
                float a = bc[g];
#pragma unroll
                for (int p = 0; p < SPLIT1; p++) a += g_cqk_part[p][n * Hh + g];
                s += a * bk[g];
            }
#pragma unroll
            for (int o = 16; o > 0; o >>= 1) s += __shfl_xor_sync(0xffffffffu, s, o);
            if (lane == 0) g_c_part[by][n] = s;
        }
        return;
    }

    __shared__ float As[32 * 33];
    __shared__ float Bs[32 * 68];

    const int h0 = blockIdx.x * 64;
    const int tn = tid >> 4;
    const int th = tid & 15;

    float4 acc[4];
#pragma unroll
    for (int i = 0; i < 4; i++) acc[i] = make_float4(0.f, 0.f, 0.f, 0.f);

    for (int c = 0; c < 6; c++) {
        const int k0 = kbase + c * 32;
        // A tile: sum of 8 partials + bias (all L2-resident)
#pragma unroll
        for (int r = 0; r < 2; r++) {
            int idx = tid + 128 * r;
            int n = idx >> 3;
            int k4 = (idx & 7) * 4;
            float4 s = *(const float4*)(bc + k0 + k4);
#pragma unroll
            for (int p = 0; p < SPLIT1; p++) {
                float4 v = *(const float4*)(&g_cqk_part[p][n * Hh + k0 + k4]);
                s.x += v.x; s.y += v.y; s.z += v.z; s.w += v.w;
            }
            float* d = &As[n * 33 + k4];
            d[0] = s.x; d[1] = s.y; d[2] = s.z; d[3] = s.w;
        }
        // B tile: 32k x 64h contiguous
#pragma unroll
        for (int r = 0; r < 4; r++) {
            int idx = tid + 128 * r;
            int kk = idx >> 4;
            int h4 = (idx & 15) * 4;
            *(float4*)&Bs[kk * 68 + h4] =
                *(const float4*)(Wk + (size_t)(k0 + kk) * Hh + h0 + h4);
        }
        __syncthreads();
#pragma unroll
        for (int kk = 0; kk < 32; kk++) {
            float4 b4 = *(float4*)&Bs[kk * 68 + th * 4];
#pragma unroll
            for (int i = 0; i < 4; i++) {
                float a = As[(tn * 4 + i) * 33 + kk];
                acc[i].x += a * b4.x;
                acc[i].y += a * b4.y;
                acc[i].z += a * b4.z;
                acc[i].w += a * b4.w;
            }
        }
        __syncthreads();
    }
#pragma unroll
    for (int i = 0; i < 4; i++)
        *(float4*)&g_v_part[by][(tn * 4 + i) * Hh + h0 + th * 4] = acc[i];
}

// ---------------------------------------------------------------------------
// Kernel 3: score[n,k] = pe1[n,k,:].v[n,:] + c[n], masked (ck_mask int32)
// 128 blocks x 256: block b -> n = b>>2, k-group = (b&3)*8 + warp.
// v[n] (sum of 4 partials) staged in smem; warp-per-k float4 dot.
// ---------------------------------------------------------------------------
__global__ __launch_bounds__(256) void score_kernel(const float* __restrict__ pe1,
                                                    const int* __restrict__ ckm,
                                                    float* __restrict__ out) {
    __shared__ float v_sm[Hh];
    const int b   = blockIdx.x;
    const int n   = b >> 2;
    const int kg  = b & 3;
    const int tid = threadIdx.x;

    if (tid < 192) {
        float4 s = make_float4(0.f, 0.f, 0.f, 0.f);
#pragma unroll
        for (int p = 0; p < SPLIT2; p++) {
            float4 v = ((const float4*)(&g_v_part[p][n * Hh]))[tid];
            s.x += v.x; s.y += v.y; s.z += v.z; s.w += v.w;
        }
        ((float4*)v_sm)[tid] = s;
    }
    float c = g_c_part[0][n] + g_c_part[1][n] + g_c_part[2][n] + g_c_part[3][n];
    __syncthreads();

    const int w    = tid >> 5;
    const int lane = tid & 31;
    const int k    = kg * 8 + w;
    const float4* p4 = (const float4*)(pe1 + (size_t)(n * Kk + k) * Hh);
    const float4* v4 = (const float4*)v_sm;
    float s = 0.f;
#pragma unroll
    for (int m = 0; m < 6; m++) {
        float4 a = p4[lane + 32 * m];
        float4 v = v4[lane + 32 * m];
        s += a.x * v.x + a.y * v.y + a.z * v.z + a.w * v.w;
    }
#pragma unroll
    for (int o = 16; o > 0; o >>= 1) s += __shfl_xor_sync(0xffffffffu, s, o);
    if (lane == 0)
        out[OFF_SCORE + n * Kk + k] = (ckm[n * Kk + k] != 0) ? (s + c) : NEGINF;
}

// ---------------------------------------------------------------------------
// Kernel 4: gather copy (float4 vectorized). Masks/tokens are int32.
// units: 786432 enc + 6144 use + 1024 mask + 1024 idx = 794624
// ---------------------------------------------------------------------------
__global__ __launch_bounds__(256) void gather_kernel(const float* __restrict__ pe0,
                                                     const float* __restrict__ pe1,
                                                     const int* __restrict__ pm,
                                                     const int* __restrict__ label,
                                                     const int* __restrict__ ptok,
                                                     float* __restrict__ out) {
    unsigned u = blockIdx.x * blockDim.x + threadIdx.x;
    if (u < 786432u) {
        int n = u / 24576u;
        int rem = u % 24576u;
        int l = label[n];
        float4 v = *(const float4*)(pe0 + (size_t)(n * Kk + l) * (Tt * Hh) + (size_t)rem * 4);
        *(float4*)(out + OFF_ENC + (size_t)u * 4) = v;
    } else if (u < 786432u + 6144u) {
        int i = u - 786432u;
        int n = i / 192, rem = i % 192;
        int l = label[n];
        float4 v = *(const float4*)(pe1 + (size_t)(n * Kk + l) * Hh + rem * 4);
        *(float4*)(out + OFF_USE + (size_t)i * 4) = v;
    } else if (u < 786432u + 6144u + 1024u) {
        int i = u - 792576u;
        int n = i / 32, rem = i % 32;
        int l = label[n];
        int4 m = *(const int4*)(pm + (size_t)(n * Kk + l) * Tt + rem * 4);
        float4 v = make_float4(m.x ? 1.f : 0.f, m.y ? 1.f : 0.f,
                               m.z ? 1.f : 0.f, m.w ? 1.f : 0.f);
        *(float4*)(out + OFF_MASK + (size_t)i * 4) = v;
    } else if (u < 794624u) {
        int i = u - 793600u;
        int n = i / 32, rem = i % 32;
        int l = label[n];
        int4 t = *(const int4*)(ptok + (size_t)(n * Kk + l) * Tt + rem * 4);
        float4 v = make_float4((float)t.x, (float)t.y, (float)t.z, (float)t.w);
        *(float4*)(out + OFF_IDX + (size_t)i * 4) = v;
    }
}

// ---------------------------------------------------------------------------
extern "C" void kernel_launch(void* const* d_in, const int* in_sizes, int n_in,
                              void* d_out, int out_size) {
    const float* ce1   = (const float*)d_in[0];
    const float* tk    = (const float*)d_in[1];
    const float* pe0   = (const float*)d_in[2];
    const float* pe1   = (const float*)d_in[3];
    const int*   pm    = (const int*)d_in[4];
    const int*   ckm   = (const int*)d_in[5];
    const int*   label = (const int*)d_in[6];
    const int*   ptok  = (const int*)d_in[7];
    const float* Wc    = (const float*)d_in[8];
    const float* bc    = (const float*)d_in[9];
    const float* Wk    = (const float*)d_in[10];
    const float* bk    = (const float*)d_in[11];
    float* out = (float*)d_out;

    gemm1_kernel<<<dim3(12, SPLIT1), 128>>>(ce1, tk, Wc);
    gemm2_kernel<<<dim3(13, SPLIT2), 128>>>(Wk, bk, bc);
    score_kernel<<<128, 256>>>(pe1, ckm, out);
    gather_kernel<<<3104, 256>>>(pe0, pe1, pm, label, ptok, out);
}